// round 4
// baseline (speedup 1.0000x reference)
#include <cuda_runtime.h>
#include <cuda_fp16.h>
#include <math_constants.h>
#include <stdint.h>

#define BB 2
#define NN 512
#define HH 128
#define DD 128
#define TT 8
#define ZK 256
#define JC 16   // sender (x) chunks
#define TJ 32   // senders per chunk
#define TY 64   // receivers (y) per CTA tile

// ---------------- device scratch (module-load allocated, no runtime alloc) ----
__device__ float d_A1[BB*NN*DD];    // z@Wm1 + bm1 + bme + (g@Wmg + bmg)   (receiver y side)
__device__ float d_A2[BB*NN*DD];    // z@Wm2 + bm2                          (sender x side)
__device__ float d_O1[BB*NN*DD];    // z@Wo1 + bo1
__device__ float d_P1[BB*NN*TT];    // z@Wt1 + bt1 + bte + (g@Wtg + btg)   (y side)
__device__ float d_P2[BB*NN*TT];    // z@Wt2 + bt2                          (x side)
__device__ float d_G [BB*DD];
__device__ float d_Gt[BB*TT];
__device__ float d_pmax[BB*JC*NN*DD];   // partial masked maxes, 8 MB

// ---------------- graph-feature projections ---------------------------------
__global__ void k_graph(const float* __restrict__ gf, const float* __restrict__ Wmg,
                        const float* __restrict__ bme, const float* __restrict__ bmg,
                        const float* __restrict__ Wtg, const float* __restrict__ bte,
                        const float* __restrict__ btg)
{
    int t = threadIdx.x;
    int b = t >> 7, d = t & 127;
    float s = 0.f;
    #pragma unroll 4
    for (int h = 0; h < HH; ++h) s = fmaf(gf[b*HH + h], Wmg[h*DD + d], s);
    d_G[b*DD + d] = s + bme[d] + bmg[d];
    if (t < 16) {
        int b2 = t >> 3, tt = t & 7;
        float s2 = 0.f;
        #pragma unroll 4
        for (int h = 0; h < HH; ++h) s2 = fmaf(gf[b2*HH + h], Wtg[h*TT + tt], s2);
        d_Gt[b2*TT + tt] = s2 + bte[tt] + btg[tt];
    }
}

// ---------------- per-node linears -------------------------------------------
__global__ __launch_bounds__(256) void k_node(
    const float* __restrict__ node, const float* __restrict__ hidden,
    const float* __restrict__ Wm1, const float* __restrict__ bm1,
    const float* __restrict__ Wm2, const float* __restrict__ bm2,
    const float* __restrict__ Wo1, const float* __restrict__ bo1,
    const float* __restrict__ Wt1, const float* __restrict__ bt1,
    const float* __restrict__ Wt2, const float* __restrict__ bt2)
{
    __shared__ float zt[8][ZK];
    const int tid = threadIdx.x;
    const int g0 = blockIdx.x * 8;                 // 8 (b,n) rows per block
    for (int idx = tid; idx < 8*ZK; idx += 256) {
        int r = idx >> 8, c = idx & 255;
        size_t gid = (size_t)(g0 + r);
        zt[r][c] = (c < HH) ? node[gid*HH + c] : hidden[gid*HH + (c - HH)];
    }
    __syncthreads();
    const int d = tid & 127, nh = tid >> 7;
    float s1[4] = {0,0,0,0}, s2[4] = {0,0,0,0}, so[4] = {0,0,0,0};
    #pragma unroll 4
    for (int k = 0; k < ZK; ++k) {
        float w1 = Wm1[k*DD + d], w2 = Wm2[k*DD + d], wo = Wo1[k*DD + d];
        #pragma unroll
        for (int r = 0; r < 4; ++r) {
            float z = zt[nh*4 + r][k];
            s1[r] = fmaf(z, w1, s1[r]);
            s2[r] = fmaf(z, w2, s2[r]);
            so[r] = fmaf(z, wo, so[r]);
        }
    }
    #pragma unroll
    for (int r = 0; r < 4; ++r) {
        int gid = g0 + nh*4 + r;
        int b = gid >> 9;
        d_A1[(size_t)gid*DD + d] = s1[r] + bm1[d] + d_G[b*DD + d];
        d_A2[(size_t)gid*DD + d] = s2[r] + bm2[d];
        d_O1[(size_t)gid*DD + d] = so[r] + bo1[d];
    }
    if (tid < 128) {     // triplet projections: row r (0..7), t (0..7), which (P1/P2)
        int r = tid >> 4, tt = (tid >> 1) & 7, which = tid & 1;
        const float* W = which ? Wt2 : Wt1;
        float s = 0.f;
        #pragma unroll 4
        for (int k = 0; k < ZK; ++k) s = fmaf(zt[r][k], W[k*TT + tt], s);
        int gid = g0 + r, b = gid >> 9;
        if (which) d_P2[gid*TT + tt] = s + bt2[tt];
        else       d_P1[gid*TT + tt] = s + bt1[tt] + d_Gt[b*TT + tt];
    }
}

// ---------------- fused edge pass --------------------------------------------
// smem byte offsets
#define OFF_WT   0          // half  sWt[136][136]  (W^T: [n][k], stride 136)  36992 B
#define OFF_A    36992      // half  sA [64][136]   (edge tile fp16)           17408 B
#define OFF_A1   54400      // float sA1[64][132]                              33792 B
#define OFF_P1   88192      // float sP1[64][8]                                 2048 B
#define OFF_A2   90240      // float sA2[128]                                    512 B
#define OFF_ADJ  90752      // float sAdj[64]                                    256 B
#define OFF_P2   91008      // float sP2[8]                                       32 B
#define SMEM_TOTAL 91040

// mma.sync m16n8k16 fragment thread mapping (g = lane>>2, tig = lane&3):
// A: reg0={A[g][2t],A[g][2t+1]} reg1={A[g+8][..]} reg2={A[g][2t+8..]} reg3={A[g+8][2t+8..]}
// B: reg0={B[2t][g],B[2t+1][g]} reg1={B[2t+8][g],B[2t+9][g]}     (from sWt[n][k], k pairs)
// C: c0=C[g][2t] c1=C[g][2t+1] c2=C[g+8][2t] c3=C[g+8][2t+1]
template<int NT0, int NTCOUNT>
__device__ __forceinline__ void edge_tiles(
    const __half* sA, const __half* sWt, const float* sA1,
    const float* sA2, const float* sAdj, const float* sP1, const float* sP2,
    float* rmax, float* tri0, float* tri1, int rm, int g, int tig)
{
    uint32_t Af[8][4];
    const __half* pa = sA + (rm + g)*136 + 2*tig;
    #pragma unroll
    for (int ks = 0; ks < 8; ++ks) {
        Af[ks][0] = *reinterpret_cast<const uint32_t*>(pa + ks*16);
        Af[ks][1] = *reinterpret_cast<const uint32_t*>(pa + ks*16 + 8*136);
        Af[ks][2] = *reinterpret_cast<const uint32_t*>(pa + ks*16 + 8);
        Af[ks][3] = *reinterpret_cast<const uint32_t*>(pa + ks*16 + 8*136 + 8);
    }
    #pragma unroll
    for (int t = 0; t < NTCOUNT; ++t) {
        const int nt = NT0 + t;
        const int cn = nt * 8;
        float a0 = 0.f, a1 = 0.f, a2 = 0.f, a3 = 0.f;
        const __half* pb = sWt + (cn + g)*136 + 2*tig;
        #pragma unroll
        for (int ks = 0; ks < 8; ++ks) {
            uint32_t b0 = *reinterpret_cast<const uint32_t*>(pb + ks*16);
            uint32_t b1 = *reinterpret_cast<const uint32_t*>(pb + ks*16 + 8);
            asm volatile(
                "mma.sync.aligned.m16n8k16.row.col.f32.f16.f16.f32 "
                "{%0,%1,%2,%3}, {%4,%5,%6,%7}, {%8,%9}, {%0,%1,%2,%3};\n"
                : "+f"(a0), "+f"(a1), "+f"(a2), "+f"(a3)
                : "r"(Af[ks][0]), "r"(Af[ks][1]), "r"(Af[ks][2]), "r"(Af[ks][3]),
                  "r"(b0), "r"(b1));
        }
        if (nt < 16) {   // D columns: add A1(y)+A2(x), mask by adj, running max
            const int c = cn + 2*tig;
            float2 u0 = *reinterpret_cast<const float2*>(sA1 + (rm+g)*132 + c);
            float2 u1 = *reinterpret_cast<const float2*>(sA1 + (rm+g+8)*132 + c);
            float ax = sA2[c], ay = sA2[c+1];
            float j0 = sAdj[rm+g], j1 = sAdj[rm+g+8];
            rmax[4*t+0] = fmaxf(rmax[4*t+0], (a0 + u0.x + ax) * j0);
            rmax[4*t+1] = fmaxf(rmax[4*t+1], (a1 + u0.y + ay) * j0);
            rmax[4*t+2] = fmaxf(rmax[4*t+2], (a2 + u1.x + ax) * j1);
            rmax[4*t+3] = fmaxf(rmax[4*t+3], (a3 + u1.y + ay) * j1);
        } else {         // triplet columns 128..135: add P1(y)+P2(x), relu, store
            const int tt = 2*tig;
            float p2a = sP2[tt], p2b = sP2[tt+1];
            float2 o0, o1;
            o0.x = fmaxf(a0 + sP1[(rm+g)*8 + tt]     + p2a, 0.f);
            o0.y = fmaxf(a1 + sP1[(rm+g)*8 + tt + 1] + p2b, 0.f);
            o1.x = fmaxf(a2 + sP1[(rm+g+8)*8 + tt]     + p2a, 0.f);
            o1.y = fmaxf(a3 + sP1[(rm+g+8)*8 + tt + 1] + p2b, 0.f);
            *reinterpret_cast<float2*>(tri0 + tt) = o0;
            *reinterpret_cast<float2*>(tri1 + tt) = o1;
        }
    }
}

__global__ __launch_bounds__(256) void k_edge(
    const float* __restrict__ edge, const float* __restrict__ adj,
    const float* __restrict__ Wme, const float* __restrict__ Wte,
    float* __restrict__ out_tri)
{
    extern __shared__ char smem[];
    __half* sWt  = reinterpret_cast<__half*>(smem + OFF_WT);
    __half* sA   = reinterpret_cast<__half*>(smem + OFF_A);
    float*  sA1  = reinterpret_cast<float*>(smem + OFF_A1);
    float*  sP1  = reinterpret_cast<float*>(smem + OFF_P1);
    float*  sA2  = reinterpret_cast<float*>(smem + OFF_A2);
    float*  sAdj = reinterpret_cast<float*>(smem + OFF_ADJ);
    float*  sP2  = reinterpret_cast<float*>(smem + OFF_P2);

    const int tid = threadIdx.x;
    const int xc = blockIdx.x, yt = blockIdx.y, b = blockIdx.z;
    const int y0 = yt * TY;

    // stage W^T (fp16) once per CTA: sWt[n][k], n in [0,136), k in [0,128)
    for (int idx = tid; idx < HH*DD; idx += 256) {       // Wme: [k][n] gmem-coalesced
        int k = idx >> 7, n = idx & 127;
        sWt[n*136 + k] = __float2half_rn(Wme[idx]);
    }
    for (int idx = tid; idx < HH*TT; idx += 256) {       // Wte
        int k = idx >> 3, t = idx & 7;
        sWt[(128 + t)*136 + k] = __float2half_rn(Wte[idx]);
    }
    // stage receiver-side A1, P1 once per CTA
    for (int idx = tid; idx < TY*DD; idx += 256)
        sA1[(idx >> 7)*132 + (idx & 127)] = d_A1[((size_t)b*NN + y0)*DD + idx];
    for (int idx = tid; idx < TY*TT; idx += 256)
        sP1[idx] = d_P1[((size_t)b*NN + y0)*TT + idx];

    const int warp = tid >> 5, lane = tid & 31;
    const int g = lane >> 2, tig = lane & 3;
    const int rm = (warp & 3) * 16;

    float rmax[32];
    #pragma unroll
    for (int i = 0; i < 32; ++i) rmax[i] = -CUDART_INF_F;

    for (int jx = 0; jx < TJ; ++jx) {
        const int x = xc * TJ + jx;
        __syncthreads();   // previous iter readers done (also orders initial staging)

        // stage edge tile [64 y][128 h] fp32 -> fp16 smem (stride 136 halves)
        const float4* ep4 = reinterpret_cast<const float4*>(
            edge + (((size_t)b*NN + x)*NN + y0)*DD);
        #pragma unroll
        for (int i = 0; i < 8; ++i) {
            int idx = tid + 256*i;
            int r = idx >> 5, q = idx & 31;
            float4 f = ep4[r*32 + q];
            __half2 h01 = __floats2half2_rn(f.x, f.y);
            __half2 h23 = __floats2half2_rn(f.z, f.w);
            uint2 u;
            u.x = *reinterpret_cast<uint32_t*>(&h01);
            u.y = *reinterpret_cast<uint32_t*>(&h23);
            *reinterpret_cast<uint2*>(sA + r*136 + 4*q) = u;
        }
        if (tid < 128)        sA2[tid]       = d_A2[((size_t)b*NN + x)*DD + tid];
        else if (tid < 192)   sAdj[tid-128]  = adj[((size_t)b*NN + x)*NN + y0 + (tid-128)];
        else if (tid < 200)   sP2[tid-192]   = d_P2[((size_t)b*NN + x)*TT + (tid-192)];
        __syncthreads();

        float* tri0 = out_tri + (((size_t)b*NN + x)*NN + y0 + rm + g)*TT;
        if (warp < 4)
            edge_tiles<0, 8>(sA, sWt, sA1, sA2, sAdj, sP1, sP2, rmax, tri0, tri0 + 8*TT, rm, g, tig);
        else
            edge_tiles<8, 9>(sA, sWt, sA1, sA2, sAdj, sP1, sP2, rmax, tri0, tri0 + 8*TT, rm, g, tig);
    }

    // write partial maxes for this x-chunk
    const int nt0 = (warp < 4) ? 0 : 8;
    #pragma unroll
    for (int t = 0; t < 8; ++t) {
        int c = (nt0 + t)*8 + 2*tig;
        size_t base = (((size_t)(b*JC + xc))*NN + y0 + rm + g)*DD + c;
        float2 v0 = { rmax[4*t+0], rmax[4*t+1] };
        float2 v1 = { rmax[4*t+2], rmax[4*t+3] };
        *reinterpret_cast<float2*>(d_pmax + base)          = v0;
        *reinterpret_cast<float2*>(d_pmax + base + 8*DD)   = v1;
    }
}

// ---------------- final reduce + output linear -------------------------------
__global__ __launch_bounds__(256) void k_reduce(
    const float* __restrict__ Wo2, const float* __restrict__ bo2,
    float* __restrict__ out_ret)
{
    __shared__ float sM[4][128];
    const int tid = threadIdx.x;
    const int gr0 = blockIdx.x * 4;     // 4 (b,y) rows per block
    for (int idx = tid; idx < 512; idx += 256) {
        int r = idx >> 7, d = idx & 127;
        int gid = gr0 + r, b = gid >> 9, y = gid & 511;
        float m = -CUDART_INF_F;
        #pragma unroll
        for (int xc = 0; xc < JC; ++xc)
            m = fmaxf(m, d_pmax[(((size_t)(b*JC + xc))*NN + y)*DD + d]);
        sM[r][d] = m;
    }
    __syncthreads();
    for (int idx = tid; idx < 512; idx += 256) {
        int r = idx >> 7, d = idx & 127;
        int gid = gr0 + r;
        float s = 0.f;
        #pragma unroll 4
        for (int k = 0; k < 128; ++k) s = fmaf(sM[r][k], Wo2[k*DD + d], s);
        out_ret[(size_t)gid*DD + d] = d_O1[(size_t)gid*DD + d] + s + bo2[d];
    }
}

// ---------------- launch ------------------------------------------------------
extern "C" void kernel_launch(void* const* d_in, const int* in_sizes, int n_in,
                              void* d_out, int out_size)
{
    const float* node   = (const float*)d_in[0];
    const float* edge   = (const float*)d_in[1];
    const float* graph  = (const float*)d_in[2];
    const float* adj    = (const float*)d_in[3];
    const float* hidden = (const float*)d_in[4];
    const float* Wm1 = (const float*)d_in[5],  *bm1 = (const float*)d_in[6];
    const float* Wm2 = (const float*)d_in[7],  *bm2 = (const float*)d_in[8];
    const float* Wme = (const float*)d_in[9],  *bme = (const float*)d_in[10];
    const float* Wmg = (const float*)d_in[11], *bmg = (const float*)d_in[12];
    const float* Wo1 = (const float*)d_in[13], *bo1 = (const float*)d_in[14];
    const float* Wo2 = (const float*)d_in[15], *bo2 = (const float*)d_in[16];
    const float* Wt1 = (const float*)d_in[17], *bt1 = (const float*)d_in[18];
    const float* Wt2 = (const float*)d_in[19], *bt2 = (const float*)d_in[20];
    const float* Wte = (const float*)d_in[21], *bte = (const float*)d_in[22];
    const float* Wtg = (const float*)d_in[23], *btg = (const float*)d_in[24];

    float* out_ret = (float*)d_out;                   // [2,512,128]
    float* out_tri = out_ret + (size_t)BB*NN*DD;      // [2,512,512,8]

    k_graph<<<1, 256>>>(graph, Wmg, bme, bmg, Wtg, bte, btg);
    k_node<<<BB*NN/8, 256>>>(node, hidden, Wm1, bm1, Wm2, bm2,
                             Wo1, bo1, Wt1, bt1, Wt2, bt2);
    cudaFuncSetAttribute(k_edge, cudaFuncAttributeMaxDynamicSharedMemorySize, SMEM_TOTAL);
    k_edge<<<dim3(JC, NN/TY, BB), 256, SMEM_TOTAL>>>(edge, adj, Wme, Wte, out_tri);
    k_reduce<<<BB*NN/4, 256>>>(Wo2, bo2, out_ret);
}

// round 6
// speedup vs baseline: 1.0199x; 1.0199x over previous
#include <cuda_runtime.h>
#include <cuda_fp16.h>
#include <stdint.h>

#define BB 2
#define NN 512
#define HH 128
#define DD 128
#define TT 8
#define ZK 256
#define JC 8      // sender (x) chunks
#define TJ 64     // senders per chunk
#define TY 64     // receivers (y) per CTA tile

// ---------------- device scratch ------------------------------------------
__device__ float d_A1[BB*NN*DD];    // z@Wm1 + bm1 + bme + (g@Wmg + bmg)
__device__ float d_A2[BB*NN*DD];    // z@Wm2 + bm2
__device__ float d_O1[BB*NN*DD];    // z@Wo1 + bo1
__device__ float d_P1[BB*NN*TT];    // z@Wt1 + bt1 + bte + (g@Wtg + btg)
__device__ float d_P2[BB*NN*TT];    // z@Wt2 + bt2
__device__ float d_G [BB*DD];
__device__ float d_Gt[BB*TT];
__device__ float d_pmax[BB*JC*NN*DD];   // partial masked maxes, 4 MB

// ---------------- small helpers ---------------------------------------------
__device__ __forceinline__ uint32_t smem_u32(const void* p) {
    uint32_t a;
    asm("{ .reg .u64 t; cvta.to.shared.u64 t, %1; cvt.u32.u64 %0, t; }"
        : "=r"(a) : "l"(p));
    return a;
}
__device__ __forceinline__ void cp16(uint32_t s, const void* g) {
    asm volatile("cp.async.cg.shared.global [%0], [%1], 16;"
                 :: "r"(s), "l"(__cvta_generic_to_global(g)));
}
#define CP_COMMIT() asm volatile("cp.async.commit_group;" ::: "memory")
#define CP_WAIT0()  asm volatile("cp.async.wait_group 0;" ::: "memory")

#define MMA4(acc, a0, a1, a2, a3, b0, b1)                                   \
    asm volatile("mma.sync.aligned.m16n8k16.row.col.f32.f16.f16.f32 "       \
                 "{%0,%1,%2,%3}, {%4,%5,%6,%7}, {%8,%9}, {%0,%1,%2,%3};"    \
                 : "+f"((acc)[0]), "+f"((acc)[1]), "+f"((acc)[2]), "+f"((acc)[3]) \
                 : "r"(a0), "r"(a1), "r"(a2), "r"(a3), "r"(b0), "r"(b1))

// ---------------- graph-feature projections ---------------------------------
__global__ void k_graph(const float* __restrict__ gf, const float* __restrict__ Wmg,
                        const float* __restrict__ bme, const float* __restrict__ bmg,
                        const float* __restrict__ Wtg, const float* __restrict__ bte,
                        const float* __restrict__ btg)
{
    int t = threadIdx.x;
    int b = t >> 7, d = t & 127;
    float s = 0.f;
    #pragma unroll 4
    for (int h = 0; h < HH; ++h) s = fmaf(gf[b*HH + h], Wmg[h*DD + d], s);
    d_G[b*DD + d] = s + bme[d] + bmg[d];
    if (t < 16) {
        int b2 = t >> 3, tt = t & 7;
        float s2 = 0.f;
        #pragma unroll 4
        for (int h = 0; h < HH; ++h) s2 = fmaf(gf[b2*HH + h], Wtg[h*TT + tt], s2);
        d_Gt[b2*TT + tt] = s2 + bte[tt] + btg[tt];
    }
}

// ---------------- per-node linears -------------------------------------------
__global__ __launch_bounds__(256) void k_node(
    const float* __restrict__ node, const float* __restrict__ hidden,
    const float* __restrict__ Wm1, const float* __restrict__ bm1,
    const float* __restrict__ Wm2, const float* __restrict__ bm2,
    const float* __restrict__ Wo1, const float* __restrict__ bo1,
    const float* __restrict__ Wt1, const float* __restrict__ bt1,
    const float* __restrict__ Wt2, const float* __restrict__ bt2)
{
    __shared__ float zt[8][ZK];
    const int tid = threadIdx.x;
    const int g0 = blockIdx.x * 8;
    for (int idx = tid; idx < 8*ZK; idx += 256) {
        int r = idx >> 8, c = idx & 255;
        size_t gid = (size_t)(g0 + r);
        zt[r][c] = (c < HH) ? node[gid*HH + c] : hidden[gid*HH + (c - HH)];
    }
    __syncthreads();
    const int d = tid & 127, nh = tid >> 7;
    float s1[4] = {0,0,0,0}, s2[4] = {0,0,0,0}, so[4] = {0,0,0,0};
    #pragma unroll 4
    for (int k = 0; k < ZK; ++k) {
        float w1 = Wm1[k*DD + d], w2 = Wm2[k*DD + d], wo = Wo1[k*DD + d];
        #pragma unroll
        for (int r = 0; r < 4; ++r) {
            float z = zt[nh*4 + r][k];
            s1[r] = fmaf(z, w1, s1[r]);
            s2[r] = fmaf(z, w2, s2[r]);
            so[r] = fmaf(z, wo, so[r]);
        }
    }
    #pragma unroll
    for (int r = 0; r < 4; ++r) {
        int gid = g0 + nh*4 + r;
        int b = gid >> 9;
        d_A1[(size_t)gid*DD + d] = s1[r] + bm1[d] + d_G[b*DD + d];
        d_A2[(size_t)gid*DD + d] = s2[r] + bm2[d];
        d_O1[(size_t)gid*DD + d] = so[r] + bo1[d];
    }
    if (tid < 128) {
        int r = tid >> 4, tt = (tid >> 1) & 7, which = tid & 1;
        const float* W = which ? Wt2 : Wt1;
        float s = 0.f;
        #pragma unroll 4
        for (int k = 0; k < ZK; ++k) s = fmaf(zt[r][k], W[k*TT + tt], s);
        int gid = g0 + r, b = gid >> 9;
        if (which) d_P2[gid*TT + tt] = s + bt2[tt];
        else       d_P1[gid*TT + tt] = s + bt1[tt] + d_Gt[b*TT + tt];
    }
}

// ---------------- fused edge pass (mma.sync, pipelined) ----------------------
// smem layout (bytes)
#define OFF_F0   0          // float edge buf0 [64][128]   32768
#define OFF_F1   32768      // float edge buf1             32768
#define OFF_C0   65536      // consts slot0: A2[128] adj[64] P2[8]  (800 used, 1024 pad)
#define OFF_C1   66560
#define OFF_SA   67584      // half sA[64][136]            17408
#define OFF_WTRI 84992      // half sWtri[8][128]           2048
#define OFF_SA1  87040      // float sA1[64][132]          33792
#define SMEM_EDGE 120832

__device__ __forceinline__ void stage_tile(
    uint32_t sb, int s, int tid, const float* __restrict__ edge,
    const float* __restrict__ adjp, int b, int x, int y0)
{
    uint32_t fb = sb + (s ? OFF_F1 : OFF_F0);
    const float* ep = edge + (((size_t)b*NN + x)*NN + y0)*DD;
    #pragma unroll
    for (int i = 0; i < 4; ++i) {
        int c = tid + i*512;
        cp16(fb + c*16, ep + c*4);
    }
    if (tid < 50) {
        uint32_t cb = sb + (s ? OFF_C1 : OFF_C0);
        const float* src;
        if (tid < 32)      src = d_A2 + ((size_t)b*NN + x)*DD + tid*4;
        else if (tid < 48) src = adjp + ((size_t)b*NN + x)*NN + y0 + (tid-32)*4;
        else               src = d_P2 + ((size_t)b*NN + x)*TT + (tid-48)*4;
        cp16(cb + tid*16, src);
    }
}

__global__ __launch_bounds__(512, 1) void k_edge(
    const float* __restrict__ edge, const float* __restrict__ adjp,
    const float* __restrict__ Wme, const float* __restrict__ Wte,
    float* __restrict__ out_tri)
{
    extern __shared__ char smem[];
    const uint32_t sb = smem_u32(smem);
    float* sA1   = reinterpret_cast<float*>(smem + OFF_SA1);
    __half* sWtri = reinterpret_cast<__half*>(smem + OFF_WTRI);

    const int tid = threadIdx.x;
    const int w = tid >> 5, lane = tid & 31;
    const int m0 = (w & 3) * 16;          // m-tile base row
    const int cg = w >> 2;                // col group: cols cg*32..cg*32+31 (+tri for cg3)
    const int g = lane >> 2, tig = lane & 3;
    const int xc = blockIdx.x, yt = blockIdx.y, b = blockIdx.z;
    const int y0 = yt * TY;
    const int x0 = xc * TJ;

    // ---- one-time: A1 -> smem (padded stride 132) ----
    {
        const float4* a1src = reinterpret_cast<const float4*>(
            d_A1 + ((size_t)b*NN + y0)*DD);
        #pragma unroll
        for (int i = 0; i < 4; ++i) {
            int idx = tid + i*512;                       // 0..2047 float4
            float4 v = a1src[idx];
            *reinterpret_cast<float4*>(&sA1[(idx >> 5)*132 + (idx & 31)*4]) = v;
        }
    }
    // ---- one-time: tri weights -> smem ([t][k] half, stride 128) ----
    {
        int t = tid >> 6, k = (tid & 63) * 2;
        __half2 h = __floats2half2_rn(Wte[k*TT + t], Wte[(k+1)*TT + t]);
        *reinterpret_cast<__half2*>(&sWtri[t*128 + k]) = h;
    }
    // ---- one-time: B (Wme cols) -> registers ----
    uint32_t Br[8][4][2];
    {
        const int nb = cg*32 + g;
        #pragma unroll
        for (int ks = 0; ks < 8; ++ks) {
            const int k0 = ks*16 + 2*tig;
            #pragma unroll
            for (int t = 0; t < 4; ++t) {
                const int n = nb + t*8;
                __half2 lo = __floats2half2_rn(Wme[k0*DD + n],     Wme[(k0+1)*DD + n]);
                __half2 hi = __floats2half2_rn(Wme[(k0+8)*DD + n], Wme[(k0+9)*DD + n]);
                Br[ks][t][0] = *reinterpret_cast<uint32_t*>(&lo);
                Br[ks][t][1] = *reinterpret_cast<uint32_t*>(&hi);
            }
        }
    }
    // ---- one-time: P1 regs (tri group) ----
    float p1[4] = {0,0,0,0};
    if (cg == 3) {
        const size_t r0 = ((size_t)b*NN + y0 + m0 + g)*TT;
        p1[0] = d_P1[r0 + 2*tig];           p1[1] = d_P1[r0 + 2*tig + 1];
        p1[2] = d_P1[r0 + 8*TT + 2*tig];    p1[3] = d_P1[r0 + 8*TT + 2*tig + 1];
    }

    float rmax[16];
    #pragma unroll
    for (int i = 0; i < 16; ++i) rmax[i] = __int_as_float(0xff800000);

    // ldmatrix base address for this lane (row within sA, k-subtile select)
    const uint32_t ldmb = sb + OFF_SA
        + (uint32_t)(m0 + ((lane >> 3) & 1)*8 + (lane & 7)) * 272u
        + (uint32_t)((lane >> 4) & 1) * 16u;

    // ---- prologue: stage tile 0 ----
    stage_tile(sb, 0, tid, edge, adjp, b, x0, y0);
    CP_COMMIT();

    for (int jx = 0; jx < TJ; ++jx) {
        const int s = jx & 1;
        CP_WAIT0();
        __syncthreads();                      // tile jx visible; prev iter readers done

        // convert fp32 buf -> fp16 sA (row stride 136 halves)
        {
            const float4* src = reinterpret_cast<const float4*>(
                smem + (s ? OFF_F1 : OFF_F0)) + tid*4;
            float4 v0 = src[0], v1 = src[1], v2 = src[2], v3 = src[3];
            __half2 h0 = __floats2half2_rn(v0.x, v0.y), h1 = __floats2half2_rn(v0.z, v0.w);
            __half2 h2 = __floats2half2_rn(v1.x, v1.y), h3 = __floats2half2_rn(v1.z, v1.w);
            __half2 h4 = __floats2half2_rn(v2.x, v2.y), h5 = __floats2half2_rn(v2.z, v2.w);
            __half2 h6 = __floats2half2_rn(v3.x, v3.y), h7 = __floats2half2_rn(v3.z, v3.w);
            uint4 o0, o1;
            o0.x = *reinterpret_cast<uint32_t*>(&h0); o0.y = *reinterpret_cast<uint32_t*>(&h1);
            o0.z = *reinterpret_cast<uint32_t*>(&h2); o0.w = *reinterpret_cast<uint32_t*>(&h3);
            o1.x = *reinterpret_cast<uint32_t*>(&h4); o1.y = *reinterpret_cast<uint32_t*>(&h5);
            o1.z = *reinterpret_cast<uint32_t*>(&h6); o1.w = *reinterpret_cast<uint32_t*>(&h7);
            char* dst = smem + OFF_SA + (tid >> 3)*272 + (tid & 7)*32;
            *reinterpret_cast<uint4*>(dst)      = o0;
            *reinterpret_cast<uint4*>(dst + 16) = o1;
        }
        // stage next tile into the other buffer
        if (jx + 1 < TJ) {
            stage_tile(sb, s ^ 1, tid, edge, adjp, b, x0 + jx + 1, y0);
            CP_COMMIT();
        }
        __syncthreads();                      // sA ready

        // ---- MMA ----
        float acc[4][4] = {{0,0,0,0},{0,0,0,0},{0,0,0,0},{0,0,0,0}};
        float acct[4] = {0,0,0,0};
        #pragma unroll
        for (int ks = 0; ks < 8; ++ks) {
            uint32_t a0, a1, a2, a3;
            asm volatile("ldmatrix.sync.aligned.m8n8.x4.shared.b16 {%0,%1,%2,%3}, [%4];"
                         : "=r"(a0), "=r"(a1), "=r"(a2), "=r"(a3)
                         : "r"(ldmb + (uint32_t)ks*32u));
            #pragma unroll
            for (int t = 0; t < 4; ++t)
                MMA4(acc[t], a0, a1, a2, a3, Br[ks][t][0], Br[ks][t][1]);
            if (cg == 3) {
                uint32_t b0 = *reinterpret_cast<const uint32_t*>(&sWtri[g*128 + ks*16 + 2*tig]);
                uint32_t b1 = *reinterpret_cast<const uint32_t*>(&sWtri[g*128 + ks*16 + 2*tig + 8]);
                MMA4(acct, a0, a1, a2, a3, b0, b1);
            }
        }

        // ---- fused epilogue ----
        const float* cs = reinterpret_cast<const float*>(smem + (s ? OFF_C1 : OFF_C0));
        const float aj0 = cs[128 + m0 + g];
        const float aj1 = cs[128 + m0 + 8 + g];
        #pragma unroll
        for (int t = 0; t < 4; ++t) {
            const int c = cg*32 + t*8 + 2*tig;
            float2 a2v = *reinterpret_cast<const float2*>(&cs[c]);
            float2 u0  = *reinterpret_cast<const float2*>(&sA1[(m0 + g)*132 + c]);
            float2 u1  = *reinterpret_cast<const float2*>(&sA1[(m0 + 8 + g)*132 + c]);
            rmax[4*t+0] = fmaxf(rmax[4*t+0], (acc[t][0] + u0.x + a2v.x) * aj0);
            rmax[4*t+1] = fmaxf(rmax[4*t+1], (acc[t][1] + u0.y + a2v.y) * aj0);
            rmax[4*t+2] = fmaxf(rmax[4*t+2], (acc[t][2] + u1.x + a2v.x) * aj1);
            rmax[4*t+3] = fmaxf(rmax[4*t+3], (acc[t][3] + u1.y + a2v.y) * aj1);
        }
        if (cg == 3) {
            const int x = x0 + jx;
            const float q0 = cs[192 + 2*tig], q1 = cs[192 + 2*tig + 1];
            float2 o0, o1;
            o0.x = fmaxf(acct[0] + p1[0] + q0, 0.f);
            o0.y = fmaxf(acct[1] + p1[1] + q1, 0.f);
            o1.x = fmaxf(acct[2] + p1[2] + q0, 0.f);
            o1.y = fmaxf(acct[3] + p1[3] + q1, 0.f);
            float* tp = out_tri + (((size_t)b*NN + x)*NN + y0)*TT;
            *reinterpret_cast<float2*>(&tp[(m0 + g)*TT + 2*tig])     = o0;
            *reinterpret_cast<float2*>(&tp[(m0 + 8 + g)*TT + 2*tig]) = o1;
        }
    }

    // ---- write partial maxes for this x-chunk ----
    {
        const size_t base = (((size_t)(b*JC + xc))*NN + y0 + m0 + g)*DD;
        #pragma unroll
        for (int t = 0; t < 4; ++t) {
            const int c = cg*32 + t*8 + 2*tig;
            float2 v0 = { rmax[4*t+0], rmax[4*t+1] };
            float2 v1 = { rmax[4*t+2], rmax[4*t+3] };
            *reinterpret_cast<float2*>(&d_pmax[base + c])          = v0;
            *reinterpret_cast<float2*>(&d_pmax[base + 8*DD + c])   = v1;
        }
    }
}

// ---------------- final reduce + output linear -------------------------------
__global__ __launch_bounds__(128) void k_reduce(
    const float* __restrict__ Wo2, const float* __restrict__ bo2,
    float* __restrict__ out_ret)
{
    __shared__ float sM[128];
    const int gid = blockIdx.x;            // (b, y) row
    const int b = gid >> 9, y = gid & 511;
    const int d = threadIdx.x;
    float m = __int_as_float(0xff800000);
    #pragma unroll
    for (int xc = 0; xc < JC; ++xc)
        m = fmaxf(m, d_pmax[(((size_t)(b*JC + xc))*NN + y)*DD + d]);
    sM[d] = m;
    __syncthreads();
    float s = 0.f;
    #pragma unroll 8
    for (int k = 0; k < 128; ++k) s = fmaf(sM[k], Wo2[k*DD + d], s);
    out_ret[(size_t)gid*DD + d] = d_O1[(size_t)gid*DD + d] + s + bo2[d];
}

// ---------------- launch ------------------------------------------------------
extern "C" void kernel_launch(void* const* d_in, const int* in_sizes, int n_in,
                              void* d_out, int out_size)
{
    const float* node   = (const float*)d_in[0];
    const float* edge   = (const float*)d_in[1];
    const float* graph  = (const float*)d_in[2];
    const float* adj    = (const float*)d_in[3];
    const float* hidden = (const float*)d_in[4];
    const float* Wm1 = (const float*)d_in[5],  *bm1 = (const float*)d_in[6];
    const float* Wm2 = (const float*)d_in[7],  *bm2 = (const float*)d_in[8];
    const float* Wme = (const float*)d_in[9],  *bme = (const float*)d_in[10];
    const float* Wmg = (const float*)d_in[11], *bmg = (const float*)d_in[12];
    const float* Wo1 = (const float*)d_in[13], *bo1 = (const float*)d_in[14];
    const float* Wo2 = (const float*)d_in[15], *bo2 = (const float*)d_in[16];
    const float* Wt1 = (const float*)d_in[17], *bt1 = (const float*)d_in[18];
    const float* Wt2 = (const float*)d_in[19], *bt2 = (const float*)d_in[20];
    const float* Wte = (const float*)d_in[21], *bte = (const float*)d_in[22];
    const float* Wtg = (const float*)d_in[23], *btg = (const float*)d_in[24];

    float* out_ret = (float*)d_out;                   // [2,512,128]
    float* out_tri = out_ret + (size_t)BB*NN*DD;      // [2,512,512,8]

    k_graph<<<1, 256>>>(graph, Wmg, bme, bmg, Wtg, bte, btg);
    k_node<<<BB*NN/8, 256>>>(node, hidden, Wm1, bm1, Wm2, bm2,
                             Wo1, bo1, Wt1, bt1, Wt2, bt2);
    cudaFuncSetAttribute(k_edge, cudaFuncAttributeMaxDynamicSharedMemorySize, SMEM_EDGE);
    k_edge<<<dim3(JC, NN/TY, BB), 512, SMEM_EDGE>>>(edge, adj, Wme, Wte, out_tri);
    k_reduce<<<BB*NN, 128>>>(Wo2, bo2, out_ret);
}